// round 1
// baseline (speedup 1.0000x reference)
#include <cuda_runtime.h>
#include <math.h>
#include <stdint.h>

// Problem constants
#define T_TOK   8192        // B*S tokens
#define D_IN    1024
#define HID     2048
#define D_OUT   1024
#define NEXP    8
#define TOPK    2
#define MAXROWS 17408       // 2*T + 8*128 padding
#define NTILES  (MAXROWS/128)   // 136

// -------------------- scratch (device globals, no mallocs) --------------------
__device__ int   g_topi[T_TOK * TOPK];
__device__ float g_topv[T_TOK * TOPK];
__device__ int   g_row_token[MAXROWS];
__device__ float g_row_weight[MAXROWS];
__device__ int   g_slot[T_TOK * TOPK];
__device__ int   g_tile_expert[NTILES];
__device__ float g_h [(size_t)MAXROWS * HID];     // expert fc1 output
__device__ float g_eo[(size_t)MAXROWS * D_OUT];   // expert fc2 output (weighted)
__device__ float g_hs[(size_t)T_TOK * HID];       // shared fc1 output

// ============================================================================
// Gate: logits = x @ gate_w + b ; softmax ; write expert_weights ; top-2
// one warp per token; gate_w (1024x8) cached in smem
// ============================================================================
__global__ __launch_bounds__(256) void k_gate(const float* __restrict__ x,
                                              const float* __restrict__ gw,
                                              const float* __restrict__ gb,
                                              float* __restrict__ ew_out)
{
    __shared__ float s_gw[D_IN * NEXP];
    int tid = threadIdx.x;
    for (int i = tid; i < (D_IN * NEXP) / 4; i += 256)
        ((float4*)s_gw)[i] = ((const float4*)gw)[i];
    __syncthreads();

    int warp = tid >> 5, lane = tid & 31;
    int t = blockIdx.x * 8 + warp;
    const float* xr = x + (size_t)t * D_IN;

    float acc[NEXP];
#pragma unroll
    for (int e = 0; e < NEXP; e++) acc[e] = 0.f;

    for (int d = lane; d < D_IN; d += 32) {
        float xv = xr[d];
        float4 g0 = *(const float4*)&s_gw[d * 8];
        float4 g1 = *(const float4*)&s_gw[d * 8 + 4];
        acc[0] += xv * g0.x; acc[1] += xv * g0.y;
        acc[2] += xv * g0.z; acc[3] += xv * g0.w;
        acc[4] += xv * g1.x; acc[5] += xv * g1.y;
        acc[6] += xv * g1.z; acc[7] += xv * g1.w;
    }
#pragma unroll
    for (int off = 16; off > 0; off >>= 1)
#pragma unroll
        for (int e = 0; e < NEXP; e++)
            acc[e] += __shfl_down_sync(0xffffffffu, acc[e], off);

    if (lane == 0) {
        float l[NEXP], m = -1e30f;
#pragma unroll
        for (int e = 0; e < NEXP; e++) { l[e] = acc[e] + gb[e]; m = fmaxf(m, l[e]); }
        float s = 0.f;
#pragma unroll
        for (int e = 0; e < NEXP; e++) { l[e] = expf(l[e] - m); s += l[e]; }
        float inv = 1.f / s;
#pragma unroll
        for (int e = 0; e < NEXP; e++) {
            l[e] *= inv;
            ew_out[(size_t)t * NEXP + e] = l[e];
        }
        // top-2 (first occurrence wins on ties, matching lax.top_k)
        int i0 = 0;
#pragma unroll
        for (int e = 1; e < NEXP; e++) if (l[e] > l[i0]) i0 = e;
        int i1 = (i0 == 0) ? 1 : 0;
#pragma unroll
        for (int e = 0; e < NEXP; e++) if (e != i0 && l[e] > l[i1]) i1 = e;
        float v0 = l[i0], v1 = l[i1];
        float r = 1.f / (v0 + v1);
        g_topi[t * 2 + 0] = i0;  g_topv[t * 2 + 0] = v0 * r;
        g_topi[t * 2 + 1] = i1;  g_topv[t * 2 + 1] = v1 * r;
    }
}

// ============================================================================
// Deterministic counting sort of (token, k) assignments by expert.
// Segments padded to multiples of 128 rows -> each GEMM tile is one expert.
// Single block, 1024 threads, 16 assignments/thread.
// ============================================================================
__global__ __launch_bounds__(1024) void k_sort()
{
    __shared__ int s_cnt[NEXP][1024];
    __shared__ int s_seg[NEXP + 1];
    int tid = threadIdx.x;

    // init padded arrays
    for (int i = tid; i < MAXROWS; i += 1024) {
        g_row_token[i]  = -1;
        g_row_weight[i] = 0.f;
    }

    int own[NEXP];
#pragma unroll
    for (int e = 0; e < NEXP; e++) own[e] = 0;

    int base_a = tid * 16;
#pragma unroll
    for (int j = 0; j < 16; j++) own[g_topi[base_a + j]]++;
#pragma unroll
    for (int e = 0; e < NEXP; e++) s_cnt[e][tid] = own[e];
    __syncthreads();

    // Hillis-Steele inclusive scan over 1024 threads, all 8 experts
    for (int off = 1; off < 1024; off <<= 1) {
        int v[NEXP];
#pragma unroll
        for (int e = 0; e < NEXP; e++) v[e] = (tid >= off) ? s_cnt[e][tid - off] : 0;
        __syncthreads();
#pragma unroll
        for (int e = 0; e < NEXP; e++) s_cnt[e][tid] += v[e];
        __syncthreads();
    }

    if (tid == 0) {
        int s = 0;
        for (int e = 0; e < NEXP; e++) {
            s_seg[e] = s;
            int tot = s_cnt[e][1023];
            s += ((tot + 127) / 128) * 128;
        }
        s_seg[NEXP] = s;
    }
    __syncthreads();

    int base[NEXP];
#pragma unroll
    for (int e = 0; e < NEXP; e++) base[e] = s_seg[e] + s_cnt[e][tid] - own[e];

#pragma unroll
    for (int j = 0; j < 16; j++) {
        int a = base_a + j;
        int e = g_topi[a];
        int pos = base[e]++;
        g_row_token[pos]  = a >> 1;
        g_row_weight[pos] = g_topv[a];
        g_slot[a] = pos;
    }

    // tile -> expert map
    for (int i = tid; i < NTILES; i += 1024) {
        int rs = i * 128;
        int ee = 0;
        for (int q = 0; q < NEXP; q++) if (rs >= s_seg[q + 1]) ee = q + 1;
        g_tile_expert[i] = (rs < s_seg[NEXP] && ee < NEXP) ? ee : 0;
    }
}

// ============================================================================
// SGEMM helpers: 128x128 tile, BK=16, 256 threads, 8x8 per thread.
// ============================================================================

// Expert FC1: g_h[row] = relu( x[token(row)] @ ew1[e] + eb1[e] )
__global__ __launch_bounds__(256) void k_fc1(const float* __restrict__ x,
                                             const float* __restrict__ ew1,
                                             const float* __restrict__ eb1)
{
    __shared__ float As[16][128];
    __shared__ float Bs[16][128];
    __shared__ int   toks[128];

    int bm = blockIdx.x, bn = blockIdx.y;
    int tid = threadIdx.x;
    int e = g_tile_expert[bm];
    const float* B = ew1 + (size_t)e * D_IN * HID;

    if (tid < 128) toks[tid] = g_row_token[bm * 128 + tid];
    __syncthreads();

    float acc[8][8];
#pragma unroll
    for (int i = 0; i < 8; i++)
#pragma unroll
        for (int j = 0; j < 8; j++) acc[i][j] = 0.f;

    int tx = tid & 15, ty = tid >> 4;

    for (int kt = 0; kt < D_IN; kt += 16) {
#pragma unroll
        for (int l = 0; l < 2; l++) {
            int i = tid + l * 256;
            int row = i >> 2;
            int k4 = (i & 3) * 4;
            int tok = toks[row];
            float4 v = make_float4(0.f, 0.f, 0.f, 0.f);
            if (tok >= 0) v = *(const float4*)(x + (size_t)tok * D_IN + kt + k4);
            As[k4 + 0][row] = v.x; As[k4 + 1][row] = v.y;
            As[k4 + 2][row] = v.z; As[k4 + 3][row] = v.w;
        }
#pragma unroll
        for (int l = 0; l < 2; l++) {
            int i = tid + l * 256;
            int kr = i >> 5;
            int n4 = (i & 31) * 4;
            *(float4*)&Bs[kr][n4] =
                *(const float4*)(B + (size_t)(kt + kr) * HID + bn * 128 + n4);
        }
        __syncthreads();
#pragma unroll
        for (int k = 0; k < 16; k++) {
            float4 a0 = *(float4*)&As[k][ty * 8];
            float4 a1 = *(float4*)&As[k][ty * 8 + 4];
            float4 b0 = *(float4*)&Bs[k][tx * 8];
            float4 b1 = *(float4*)&Bs[k][tx * 8 + 4];
            float a[8] = {a0.x, a0.y, a0.z, a0.w, a1.x, a1.y, a1.z, a1.w};
            float b[8] = {b0.x, b0.y, b0.z, b0.w, b1.x, b1.y, b1.z, b1.w};
#pragma unroll
            for (int i = 0; i < 8; i++)
#pragma unroll
                for (int j = 0; j < 8; j++) acc[i][j] += a[i] * b[j];
        }
        __syncthreads();
    }

    int row0 = bm * 128 + ty * 8;
    int n0 = bn * 128 + tx * 8;
    const float* bp = eb1 + (size_t)e * HID + n0;
    float bias[8];
#pragma unroll
    for (int j = 0; j < 8; j++) bias[j] = bp[j];
#pragma unroll
    for (int i = 0; i < 8; i++) {
        float4 o0, o1;
        o0.x = fmaxf(acc[i][0] + bias[0], 0.f);
        o0.y = fmaxf(acc[i][1] + bias[1], 0.f);
        o0.z = fmaxf(acc[i][2] + bias[2], 0.f);
        o0.w = fmaxf(acc[i][3] + bias[3], 0.f);
        o1.x = fmaxf(acc[i][4] + bias[4], 0.f);
        o1.y = fmaxf(acc[i][5] + bias[5], 0.f);
        o1.z = fmaxf(acc[i][6] + bias[6], 0.f);
        o1.w = fmaxf(acc[i][7] + bias[7], 0.f);
        size_t off = (size_t)(row0 + i) * HID + n0;
        *(float4*)(g_h + off) = o0;
        *(float4*)(g_h + off + 4) = o1;
    }
}

// Expert FC2: g_eo[row] = w(row) * ( g_h[row] @ ew2[e] + eb2[e] )
__global__ __launch_bounds__(256) void k_fc2(const float* __restrict__ ew2,
                                             const float* __restrict__ eb2)
{
    __shared__ float As[16][128];
    __shared__ float Bs[16][128];
    __shared__ float wts[128];

    int bm = blockIdx.x, bn = blockIdx.y;
    int tid = threadIdx.x;
    int e = g_tile_expert[bm];
    const float* B = ew2 + (size_t)e * HID * D_OUT;

    if (tid < 128) wts[tid] = g_row_weight[bm * 128 + tid];
    __syncthreads();

    float acc[8][8];
#pragma unroll
    for (int i = 0; i < 8; i++)
#pragma unroll
        for (int j = 0; j < 8; j++) acc[i][j] = 0.f;

    int tx = tid & 15, ty = tid >> 4;

    for (int kt = 0; kt < HID; kt += 16) {
#pragma unroll
        for (int l = 0; l < 2; l++) {
            int i = tid + l * 256;
            int row = i >> 2;
            int k4 = (i & 3) * 4;
            float4 v = *(const float4*)(g_h + (size_t)(bm * 128 + row) * HID + kt + k4);
            As[k4 + 0][row] = v.x; As[k4 + 1][row] = v.y;
            As[k4 + 2][row] = v.z; As[k4 + 3][row] = v.w;
        }
#pragma unroll
        for (int l = 0; l < 2; l++) {
            int i = tid + l * 256;
            int kr = i >> 5;
            int n4 = (i & 31) * 4;
            *(float4*)&Bs[kr][n4] =
                *(const float4*)(B + (size_t)(kt + kr) * D_OUT + bn * 128 + n4);
        }
        __syncthreads();
#pragma unroll
        for (int k = 0; k < 16; k++) {
            float4 a0 = *(float4*)&As[k][ty * 8];
            float4 a1 = *(float4*)&As[k][ty * 8 + 4];
            float4 b0 = *(float4*)&Bs[k][tx * 8];
            float4 b1 = *(float4*)&Bs[k][tx * 8 + 4];
            float a[8] = {a0.x, a0.y, a0.z, a0.w, a1.x, a1.y, a1.z, a1.w};
            float b[8] = {b0.x, b0.y, b0.z, b0.w, b1.x, b1.y, b1.z, b1.w};
#pragma unroll
            for (int i = 0; i < 8; i++)
#pragma unroll
                for (int j = 0; j < 8; j++) acc[i][j] += a[i] * b[j];
        }
        __syncthreads();
    }

    int row0 = bm * 128 + ty * 8;
    int n0 = bn * 128 + tx * 8;
    const float* bp = eb2 + (size_t)e * D_OUT + n0;
    float bias[8];
#pragma unroll
    for (int j = 0; j < 8; j++) bias[j] = bp[j];
#pragma unroll
    for (int i = 0; i < 8; i++) {
        float w = wts[ty * 8 + i];
        float4 o0, o1;
        o0.x = w * (acc[i][0] + bias[0]);
        o0.y = w * (acc[i][1] + bias[1]);
        o0.z = w * (acc[i][2] + bias[2]);
        o0.w = w * (acc[i][3] + bias[3]);
        o1.x = w * (acc[i][4] + bias[4]);
        o1.y = w * (acc[i][5] + bias[5]);
        o1.z = w * (acc[i][6] + bias[6]);
        o1.w = w * (acc[i][7] + bias[7]);
        size_t off = (size_t)(row0 + i) * D_OUT + n0;
        *(float4*)(g_eo + off) = o0;
        *(float4*)(g_eo + off + 4) = o1;
    }
}

// Shared FC1: g_hs[t] = relu( x[t] @ sw1 + sb1 )
__global__ __launch_bounds__(256) void k_sh1(const float* __restrict__ x,
                                             const float* __restrict__ sw1,
                                             const float* __restrict__ sb1)
{
    __shared__ float As[16][128];
    __shared__ float Bs[16][128];

    int bm = blockIdx.x, bn = blockIdx.y;
    int tid = threadIdx.x;

    float acc[8][8];
#pragma unroll
    for (int i = 0; i < 8; i++)
#pragma unroll
        for (int j = 0; j < 8; j++) acc[i][j] = 0.f;

    int tx = tid & 15, ty = tid >> 4;

    for (int kt = 0; kt < D_IN; kt += 16) {
#pragma unroll
        for (int l = 0; l < 2; l++) {
            int i = tid + l * 256;
            int row = i >> 2;
            int k4 = (i & 3) * 4;
            float4 v = *(const float4*)(x + (size_t)(bm * 128 + row) * D_IN + kt + k4);
            As[k4 + 0][row] = v.x; As[k4 + 1][row] = v.y;
            As[k4 + 2][row] = v.z; As[k4 + 3][row] = v.w;
        }
#pragma unroll
        for (int l = 0; l < 2; l++) {
            int i = tid + l * 256;
            int kr = i >> 5;
            int n4 = (i & 31) * 4;
            *(float4*)&Bs[kr][n4] =
                *(const float4*)(sw1 + (size_t)(kt + kr) * HID + bn * 128 + n4);
        }
        __syncthreads();
#pragma unroll
        for (int k = 0; k < 16; k++) {
            float4 a0 = *(float4*)&As[k][ty * 8];
            float4 a1 = *(float4*)&As[k][ty * 8 + 4];
            float4 b0 = *(float4*)&Bs[k][tx * 8];
            float4 b1 = *(float4*)&Bs[k][tx * 8 + 4];
            float a[8] = {a0.x, a0.y, a0.z, a0.w, a1.x, a1.y, a1.z, a1.w};
            float b[8] = {b0.x, b0.y, b0.z, b0.w, b1.x, b1.y, b1.z, b1.w};
#pragma unroll
            for (int i = 0; i < 8; i++)
#pragma unroll
                for (int j = 0; j < 8; j++) acc[i][j] += a[i] * b[j];
        }
        __syncthreads();
    }

    int row0 = bm * 128 + ty * 8;
    int n0 = bn * 128 + tx * 8;
    float bias[8];
#pragma unroll
    for (int j = 0; j < 8; j++) bias[j] = sb1[n0 + j];
#pragma unroll
    for (int i = 0; i < 8; i++) {
        float4 o0, o1;
        o0.x = fmaxf(acc[i][0] + bias[0], 0.f);
        o0.y = fmaxf(acc[i][1] + bias[1], 0.f);
        o0.z = fmaxf(acc[i][2] + bias[2], 0.f);
        o0.w = fmaxf(acc[i][3] + bias[3], 0.f);
        o1.x = fmaxf(acc[i][4] + bias[4], 0.f);
        o1.y = fmaxf(acc[i][5] + bias[5], 0.f);
        o1.z = fmaxf(acc[i][6] + bias[6], 0.f);
        o1.w = fmaxf(acc[i][7] + bias[7], 0.f);
        size_t off = (size_t)(row0 + i) * HID + n0;
        *(float4*)(g_hs + off) = o0;
        *(float4*)(g_hs + off + 4) = o1;
    }
}

// Shared FC2 + combine: out[t] = g_hs[t]@sw2 + sb2 + g_eo[slot0(t)] + g_eo[slot1(t)]
__global__ __launch_bounds__(256) void k_sh2(const float* __restrict__ sw2,
                                             const float* __restrict__ sb2,
                                             float* __restrict__ out)
{
    __shared__ float As[16][128];
    __shared__ float Bs[16][128];
    __shared__ int s0s[128];
    __shared__ int s1s[128];

    int bm = blockIdx.x, bn = blockIdx.y;
    int tid = threadIdx.x;

    if (tid < 128) {
        int t = bm * 128 + tid;
        s0s[tid] = g_slot[t * 2 + 0];
        s1s[tid] = g_slot[t * 2 + 1];
    }
    __syncthreads();

    float acc[8][8];
#pragma unroll
    for (int i = 0; i < 8; i++)
#pragma unroll
        for (int j = 0; j < 8; j++) acc[i][j] = 0.f;

    int tx = tid & 15, ty = tid >> 4;

    for (int kt = 0; kt < HID; kt += 16) {
#pragma unroll
        for (int l = 0; l < 2; l++) {
            int i = tid + l * 256;
            int row = i >> 2;
            int k4 = (i & 3) * 4;
            float4 v = *(const float4*)(g_hs + (size_t)(bm * 128 + row) * HID + kt + k4);
            As[k4 + 0][row] = v.x; As[k4 + 1][row] = v.y;
            As[k4 + 2][row] = v.z; As[k4 + 3][row] = v.w;
        }
#pragma unroll
        for (int l = 0; l < 2; l++) {
            int i = tid + l * 256;
            int kr = i >> 5;
            int n4 = (i & 31) * 4;
            *(float4*)&Bs[kr][n4] =
                *(const float4*)(sw2 + (size_t)(kt + kr) * D_OUT + bn * 128 + n4);
        }
        __syncthreads();
#pragma unroll
        for (int k = 0; k < 16; k++) {
            float4 a0 = *(float4*)&As[k][ty * 8];
            float4 a1 = *(float4*)&As[k][ty * 8 + 4];
            float4 b0 = *(float4*)&Bs[k][tx * 8];
            float4 b1 = *(float4*)&Bs[k][tx * 8 + 4];
            float a[8] = {a0.x, a0.y, a0.z, a0.w, a1.x, a1.y, a1.z, a1.w};
            float b[8] = {b0.x, b0.y, b0.z, b0.w, b1.x, b1.y, b1.z, b1.w};
#pragma unroll
            for (int i = 0; i < 8; i++)
#pragma unroll
                for (int j = 0; j < 8; j++) acc[i][j] += a[i] * b[j];
        }
        __syncthreads();
    }

    int row0 = bm * 128 + ty * 8;
    int n0 = bn * 128 + tx * 8;
    float bias[8];
#pragma unroll
    for (int j = 0; j < 8; j++) bias[j] = sb2[n0 + j];
#pragma unroll
    for (int i = 0; i < 8; i++) {
        int t = row0 + i;
        int s0 = s0s[ty * 8 + i];
        int s1 = s1s[ty * 8 + i];
        const float* e0 = g_eo + (size_t)s0 * D_OUT + n0;
        const float* e1 = g_eo + (size_t)s1 * D_OUT + n0;
        float4 a0 = *(const float4*)e0;
        float4 a1 = *(const float4*)(e0 + 4);
        float4 c0 = *(const float4*)e1;
        float4 c1 = *(const float4*)(e1 + 4);
        float4 o0, o1;
        o0.x = acc[i][0] + bias[0] + a0.x + c0.x;
        o0.y = acc[i][1] + bias[1] + a0.y + c0.y;
        o0.z = acc[i][2] + bias[2] + a0.z + c0.z;
        o0.w = acc[i][3] + bias[3] + a0.w + c0.w;
        o1.x = acc[i][4] + bias[4] + a1.x + c1.x;
        o1.y = acc[i][5] + bias[5] + a1.y + c1.y;
        o1.z = acc[i][6] + bias[6] + a1.z + c1.z;
        o1.w = acc[i][7] + bias[7] + a1.w + c1.w;
        size_t off = (size_t)t * D_OUT + n0;
        *(float4*)(out + off) = o0;
        *(float4*)(out + off + 4) = o1;
    }
}

// ============================================================================
extern "C" void kernel_launch(void* const* d_in, const int* in_sizes, int n_in,
                              void* d_out, int out_size)
{
    const float* x      = (const float*)d_in[0];
    const float* gate_w = (const float*)d_in[1];
    const float* gate_b = (const float*)d_in[2];
    const float* ew1    = (const float*)d_in[3];
    const float* eb1    = (const float*)d_in[4];
    const float* ew2    = (const float*)d_in[5];
    const float* eb2    = (const float*)d_in[6];
    const float* sw1    = (const float*)d_in[7];
    const float* sb1    = (const float*)d_in[8];
    const float* sw2    = (const float*)d_in[9];
    const float* sb2    = (const float*)d_in[10];
    (void)in_sizes; (void)n_in; (void)out_size;

    float* out    = (float*)d_out;                       // final [8192,1024]
    float* ew_out = out + (size_t)T_TOK * D_OUT;         // expert_weights [8192,8]

    k_gate<<<T_TOK / 8, 256>>>(x, gate_w, gate_b, ew_out);
    k_sort<<<1, 1024>>>();
    k_fc1<<<dim3(NTILES, HID / 128), 256>>>(x, ew1, eb1);
    k_fc2<<<dim3(NTILES, D_OUT / 128), 256>>>(ew2, eb2);
    k_sh1<<<dim3(T_TOK / 128, HID / 128), 256>>>(x, sw1, sb1);
    k_sh2<<<dim3(T_TOK / 128, D_OUT / 128), 256>>>(sw2, sb2, out);
}